// round 3
// baseline (speedup 1.0000x reference)
#include <cuda_runtime.h>

#define WIDTH  1024
#define HEIGHT 1024
#define RPB    16         // rows per block-strip (must divide HEIGHT)

__device__ float        g_partials[65536];
__device__ unsigned int g_count = 0;   // self-resetting; 0 before every launch

struct RowData {
    float4 v;      // 4 target values at columns c..c+3
    float  hl, hr; // column halo (c-1 clamped, c+4 clamped)
};

__device__ __forceinline__ RowData load_row(const float* __restrict__ r,
                                            int c, int cl, int cr)
{
    RowData d;
    d.v  = *reinterpret_cast<const float4*>(r + c);
    d.hl = r[cl];
    d.hr = r[cr];
    return d;
}

// Each block handles a 16-row strip of one image; the 3-row target window
// rolls through registers (each target row loaded ~1.125x instead of 3x).
// Binary-mask morphology: boundary <=> clamped 3x3 window sum in (0,9).
// BCE with t in {0,1}: bce = -log(t ? p : 1-p)  -> one __logf per pixel.
// The LAST block to finish performs the deterministic final reduction
// (fixed-order double summation), so there is only one kernel launch.
__global__ void __launch_bounds__(256)
loss_kernel(const float* __restrict__ pred, const float* __restrict__ tgt,
            float* __restrict__ out, int n_strips, double inv_n)
{
    const int strip = blockIdx.x;
    const int row0  = strip * RPB;
    const int y0    = row0 & (HEIGHT - 1);   // strip never crosses images

    const int c  = threadIdx.x << 2;
    const int cl = (c == 0) ? 0 : c - 1;
    const int cr = (c + 4 >= WIDTH) ? (WIDTH - 1) : (c + 4);

    const float* tbase = tgt  + (size_t)row0 * WIDTH;
    const float* pbase = pred + (size_t)row0 * WIDTH;

    RowData a_prev = load_row((y0 == 0) ? tbase : tbase - WIDTH, c, cl, cr);
    RowData a_cur  = load_row(tbase, c, cl, cr);

    float acc = 0.0f;    // accumulates +w*log(arg); negated at the end

    #pragma unroll
    for (int i = 0; i < RPB; i++) {
        const int y = y0 + i;
        const float* trow_next = (y == HEIGHT - 1) ? tbase + (size_t)i * WIDTH
                                                   : tbase + (size_t)(i + 1) * WIDTH;
        const RowData a_next = load_row(trow_next, c, cl, cr);

        // pred is read exactly once: stream it (evict-first) so L2 keeps target.
        const float4 p = __ldcs(reinterpret_cast<const float4*>(
                                    pbase + (size_t)i * WIDTH + c));

        const float v0 = a_prev.v.x + a_cur.v.x + a_next.v.x;
        const float v1 = a_prev.v.y + a_cur.v.y + a_next.v.y;
        const float v2 = a_prev.v.z + a_cur.v.z + a_next.v.z;
        const float v3 = a_prev.v.w + a_cur.v.w + a_next.v.w;
        const float vl = a_prev.hl  + a_cur.hl  + a_next.hl;
        const float vr = a_prev.hr  + a_cur.hr  + a_next.hr;

        const float s0 = vl + v0 + v1;
        const float s1 = v0 + v1 + v2;
        const float s2 = v1 + v2 + v3;
        const float s3 = v2 + v3 + vr;

#define PIX(S, T, P)                                                      \
        do {                                                              \
            const float arg = ((T) > 0.5f) ? (P) : (1.0f - (P));          \
            const float w   = ((S) > 0.5f && (S) < 8.5f) ? 3.0f : 1.0f;   \
            acc = fmaf(w, __logf(arg), acc);                              \
        } while (0)

        PIX(s0, a_cur.v.x, p.x);
        PIX(s1, a_cur.v.y, p.y);
        PIX(s2, a_cur.v.z, p.z);
        PIX(s3, a_cur.v.w, p.w);
#undef PIX

        a_prev = a_cur;
        a_cur  = a_next;
    }

    // Block reduction: warp shuffle, then 8 warp leaders through smem.
    #pragma unroll
    for (int o = 16; o > 0; o >>= 1)
        acc += __shfl_xor_sync(0xffffffffu, acc, o);

    __shared__ float sacc[8];
    __shared__ bool  s_last;
    const int wid  = threadIdx.x >> 5;
    const int lane = threadIdx.x & 31;
    if (lane == 0) sacc[wid] = acc;
    __syncthreads();

    if (threadIdx.x == 0) {
        float s = 0.0f;
        #pragma unroll
        for (int i = 0; i < 8; i++) s += sacc[i];
        g_partials[strip] = -s;
        __threadfence();                       // publish partial before count
        const unsigned int old = atomicAdd(&g_count, 1u);
        s_last = (old == (unsigned int)(n_strips - 1));
    }
    __syncthreads();

    if (s_last) {
        // Deterministic fixed-order double-precision reduction of all partials.
        double s = 0.0;
        for (int i = threadIdx.x; i < n_strips; i += 256)
            s += (double)g_partials[i];

        __shared__ double sd[256];
        sd[threadIdx.x] = s;
        __syncthreads();
        #pragma unroll
        for (int o = 128; o > 0; o >>= 1) {
            if (threadIdx.x < o) sd[threadIdx.x] += sd[threadIdx.x + o];
            __syncthreads();
        }
        if (threadIdx.x == 0) {
            out[0]  = (float)(sd[0] * inv_n);
            g_count = 0;                       // reset for the next graph replay
        }
    }
}

extern "C" void kernel_launch(void* const* d_in, const int* in_sizes, int n_in,
                              void* d_out, int out_size)
{
    const float* pred = (const float*)d_in[0];
    const float* tgt  = (const float*)d_in[1];
    const int n      = in_sizes[0];        // B*1*H*W
    const int rows   = n / WIDTH;          // B*H
    const int strips = rows / RPB;

    loss_kernel<<<strips, 256>>>(pred, tgt, (float*)d_out, strips,
                                 1.0 / (double)n);
}